// round 16
// baseline (speedup 1.0000x reference)
#include <cuda_runtime.h>
#include <cuda_fp16.h>

#define NN 100000
#define NE 3200000
#define INF 512
#define HID 32
#define NBLK_SCAN 98   // ceil(NN/1024)

// ---- scratch (static device globals; no allocation) ----
__device__ int   g_deg[NN];
__device__ int   g_rowstart[NN + 1];
__device__ int   g_cursor[NN];
__device__ float g_dinv[NN];
__device__ int   g_csr[NE];
__device__ int   g_bsum[NBLK_SCAN];
__device__ int   g_boff[NBLK_SCAN];
__device__ __align__(16) __half g_hsA[(size_t)NN * HID];
__device__ __align__(16) __half g_hsB[(size_t)NN * HID];

// ---------------- preprocessing ----------------

__global__ void zero_deg_kernel() {
    int i = blockIdx.x * blockDim.x + threadIdx.x;
    if (i < NN) g_deg[i] = 0;
}

__global__ void deg_kernel(const int* __restrict__ edge) {
    int e4 = blockIdx.x * blockDim.x + threadIdx.x;
    if (e4 < NE / 4) {
        int4 d = ((const int4*)(edge + NE))[e4];
        if ((unsigned)d.x < NN) atomicAdd(&g_deg[d.x], 1);
        if ((unsigned)d.y < NN) atomicAdd(&g_deg[d.y], 1);
        if ((unsigned)d.z < NN) atomicAdd(&g_deg[d.z], 1);
        if ((unsigned)d.w < NN) atomicAdd(&g_deg[d.w], 1);
    }
}

__global__ __launch_bounds__(256) void scan1_kernel() {
    __shared__ int wsum[8];
    int tid = threadIdx.x, lane = tid & 31, wid = tid >> 5;
    int i0 = blockIdx.x * 1024 + tid * 4;
    int s = 0;
    if (i0 + 3 < NN) {
        int4 v = *(const int4*)&g_deg[i0];
        s = v.x + v.y + v.z + v.w;
    } else {
        for (int j = 0; j < 4; j++) if (i0 + j < NN) s += g_deg[i0 + j];
    }
    #pragma unroll
    for (int o = 16; o > 0; o >>= 1) s += __shfl_xor_sync(0xffffffffu, s, o);
    if (lane == 0) wsum[wid] = s;
    __syncthreads();
    if (tid == 0) {
        int t = 0;
        #pragma unroll
        for (int w = 0; w < 8; w++) t += wsum[w];
        g_bsum[blockIdx.x] = t;
    }
}

__global__ __launch_bounds__(128) void scan2_kernel() {
    __shared__ int wsum[4];
    int tid = threadIdx.x, lane = tid & 31, wid = tid >> 5;
    int v = (tid < NBLK_SCAN) ? g_bsum[tid] : 0;
    int incl = v;
    #pragma unroll
    for (int o = 1; o < 32; o <<= 1) {
        int t = __shfl_up_sync(0xffffffffu, incl, o);
        if (lane >= o) incl += t;
    }
    if (lane == 31) wsum[wid] = incl;
    __syncthreads();
    int woff = 0;
    for (int w = 0; w < wid; w++) woff += wsum[w];
    int excl = woff + incl - v;
    if (tid < NBLK_SCAN) g_boff[tid] = excl;
    if (tid == NBLK_SCAN - 1) g_rowstart[NN] = excl + v;
}

__global__ __launch_bounds__(256) void scan3_kernel() {
    __shared__ int wsum[8];
    int tid = threadIdx.x, lane = tid & 31, wid = tid >> 5;
    int i0 = blockIdx.x * 1024 + tid * 4;
    int v0 = 0, v1 = 0, v2 = 0, v3 = 0;
    if (i0 + 3 < NN) {
        int4 v = *(const int4*)&g_deg[i0];
        v0 = v.x; v1 = v.y; v2 = v.z; v3 = v.w;
    } else {
        if (i0 + 0 < NN) v0 = g_deg[i0 + 0];
        if (i0 + 1 < NN) v1 = g_deg[i0 + 1];
        if (i0 + 2 < NN) v2 = g_deg[i0 + 2];
        if (i0 + 3 < NN) v3 = g_deg[i0 + 3];
    }
    int tsum = v0 + v1 + v2 + v3;
    int incl = tsum;
    #pragma unroll
    for (int o = 1; o < 32; o <<= 1) {
        int t = __shfl_up_sync(0xffffffffu, incl, o);
        if (lane >= o) incl += t;
    }
    if (lane == 31) wsum[wid] = incl;
    __syncthreads();
    int woff = 0;
    for (int w = 0; w < wid; w++) woff += wsum[w];
    int run = g_boff[blockIdx.x] + woff + incl - tsum;
    if (i0 + 0 < NN) { g_rowstart[i0 + 0] = run; g_cursor[i0 + 0] = run; g_dinv[i0 + 0] = rsqrtf((float)v0 + 1.0f); run += v0; }
    if (i0 + 1 < NN) { g_rowstart[i0 + 1] = run; g_cursor[i0 + 1] = run; g_dinv[i0 + 1] = rsqrtf((float)v1 + 1.0f); run += v1; }
    if (i0 + 2 < NN) { g_rowstart[i0 + 2] = run; g_cursor[i0 + 2] = run; g_dinv[i0 + 2] = rsqrtf((float)v2 + 1.0f); run += v2; }
    if (i0 + 3 < NN) { g_rowstart[i0 + 3] = run; g_cursor[i0 + 3] = run; g_dinv[i0 + 3] = rsqrtf((float)v3 + 1.0f); run += v3; }
}

__global__ void scatter_kernel(const int* __restrict__ edge) {
    int e4 = blockIdx.x * blockDim.x + threadIdx.x;
    if (e4 < NE / 4) {
        int4 s = ((const int4*)edge)[e4];
        int4 d = ((const int4*)(edge + NE))[e4];
        if ((unsigned)d.x < NN && (unsigned)s.x < NN) g_csr[atomicAdd(&g_cursor[d.x], 1)] = s.x;
        if ((unsigned)d.y < NN && (unsigned)s.y < NN) g_csr[atomicAdd(&g_cursor[d.y], 1)] = s.y;
        if ((unsigned)d.z < NN && (unsigned)s.z < NN) g_csr[atomicAdd(&g_cursor[d.z], 1)] = s.z;
        if ((unsigned)d.w < NN && (unsigned)s.w < NN) g_csr[atomicAdd(&g_cursor[d.w], 1)] = s.w;
    }
}

// ---------------- GEMM1: hsA = half((x0 @ W1) * dinv)  [100000x512 @ 512x32] ----------------
// Runs AFTER the CSR build (single stream) so g_dinv is valid.
#define XS_STRIDE 36
#define WT_STRIDE 38
__global__ __launch_bounds__(128) void gemm1_kernel(
    const float* __restrict__ x0, const float* __restrict__ W) {
    __shared__ __align__(16) float Xs[64 * XS_STRIDE];   // [row][k]
    __shared__ __align__(16) float Wt[32 * WT_STRIDE];   // [col][k]
    int tid = threadIdx.x;
    int ty = tid >> 3;
    int tx = tid & 7;
    int row0 = blockIdx.x * 64;

    unsigned long long acc[4][4];
    #pragma unroll
    for (int i = 0; i < 4; i++)
        #pragma unroll
        for (int j = 0; j < 4; j++) acc[i][j] = 0ull;

    for (int kc = 0; kc < INF; kc += 32) {
        #pragma unroll
        for (int t = 0; t < 8; t++) {
            int lin = tid + t * 128;
            int k = lin >> 5, c = lin & 31;
            Wt[c * WT_STRIDE + k] = W[(kc + k) * HID + c];
        }
        #pragma unroll
        for (int t = 0; t < 4; t++) {
            int lin = tid + t * 128;
            int r = lin >> 3;
            int kv = (lin & 7) << 2;
            int row = row0 + r;
            if (row >= NN) row = NN - 1;
            float4 v = *(const float4*)&x0[(size_t)row * INF + kc + kv];
            *(float4*)&Xs[r * XS_STRIDE + kv] = v;
        }
        __syncthreads();
        #pragma unroll
        for (int kp = 0; kp < 16; kp++) {
            unsigned long long a[4], b[4];
            #pragma unroll
            for (int i = 0; i < 4; i++)
                a[i] = *(const unsigned long long*)&Xs[(ty * 4 + i) * XS_STRIDE + 2 * kp];
            #pragma unroll
            for (int j = 0; j < 4; j++)
                b[j] = *(const unsigned long long*)&Wt[(tx * 4 + j) * WT_STRIDE + 2 * kp];
            #pragma unroll
            for (int i = 0; i < 4; i++)
                #pragma unroll
                for (int j = 0; j < 4; j++)
                    asm("fma.rn.f32x2 %0, %1, %2, %0;"
                        : "+l"(acc[i][j]) : "l"(a[i]), "l"(b[j]));
        }
        __syncthreads();
    }
    #pragma unroll
    for (int i = 0; i < 4; i++) {
        int row = row0 + ty * 4 + i;
        if (row < NN) {
            float dv = g_dinv[row];
            __half h[4];
            #pragma unroll
            for (int j = 0; j < 4; j++) {
                unsigned long long p = acc[i][j];
                float lo = __uint_as_float((unsigned)(p & 0xffffffffu));
                float hi = __uint_as_float((unsigned)(p >> 32));
                h[j] = __float2half((lo + hi) * dv);
            }
            *(uint2*)&g_hsA[(size_t)row * HID + tx * 4] = *(uint2*)h;
        }
    }
}

// ---------------- fused aggregate + next linear (fp16 gathers, fp32 math) ----------------
// warp per node; 8 slots x 4 lanes; lane loads uint4 = 8 halves of a row.
__global__ __launch_bounds__(256) void aggA_kernel(
    const __half* __restrict__ hs_in, __half* __restrict__ hs_out,
    const float* __restrict__ bias, const float* __restrict__ Wn) {
    __shared__ float sW[32 * 33];
    __shared__ float sb[32];
    int tid = threadIdx.x;
    for (int i = tid; i < 1024; i += 256) sW[(i >> 5) * 33 + (i & 31)] = Wn[i];
    if (tid < 32) sb[tid] = bias[tid];
    __syncthreads();

    int node = (blockIdx.x * 256 + tid) >> 5;
    int lane = tid & 31;
    int slot = lane >> 2;          // 0..7 edge slots
    int sub = lane & 3;            // 0..3 -> halves [sub*8, sub*8+8)
    int r0 = g_rowstart[node];
    int r1 = g_rowstart[node + 1];
    float2 acc[4];
    #pragma unroll
    for (int m = 0; m < 4; m++) acc[m] = make_float2(0.f, 0.f);
    int e = r0;
    for (; e + 32 <= r1; e += 32) {
        int idx = g_csr[e + lane];
        #pragma unroll
        for (int j = 0; j < 4; j++) {
            int s = __shfl_sync(0xffffffffu, idx, slot * 4 + j);
            uint4 v = *(const uint4*)&hs_in[(size_t)s * HID + sub * 8];
            __half2* h = (__half2*)&v;
            #pragma unroll
            for (int m = 0; m < 4; m++) {
                float2 f = __half22float2(h[m]);
                acc[m].x += f.x; acc[m].y += f.y;
            }
        }
    }
    int rem = r1 - e;
    if (rem) {
        int idx = (lane < rem) ? g_csr[e + lane] : 0;
        #pragma unroll
        for (int j = 0; j < 4; j++) {
            int t = slot * 4 + j;
            int s = __shfl_sync(0xffffffffu, idx, t);
            if (t < rem) {
                uint4 v = *(const uint4*)&hs_in[(size_t)s * HID + sub * 8];
                __half2* h = (__half2*)&v;
                #pragma unroll
                for (int m = 0; m < 4; m++) {
                    float2 f = __half22float2(h[m]);
                    acc[m].x += f.x; acc[m].y += f.y;
                }
            }
        }
    }
    #pragma unroll
    for (int o = 4; o < 32; o <<= 1) {
        #pragma unroll
        for (int m = 0; m < 4; m++) {
            acc[m].x += __shfl_xor_sync(0xffffffffu, acc[m].x, o);
            acc[m].y += __shfl_xor_sync(0xffffffffu, acc[m].y, o);
        }
    }
    // self term
    {
        uint4 v = *(const uint4*)&hs_in[(size_t)node * HID + sub * 8];
        __half2* h = (__half2*)&v;
        #pragma unroll
        for (int m = 0; m < 4; m++) {
            float2 f = __half22float2(h[m]);
            acc[m].x += f.x; acc[m].y += f.y;
        }
    }
    float dv = g_dinv[node];
    float x[8];
    #pragma unroll
    for (int m = 0; m < 4; m++) {
        x[2 * m + 0] = fmaxf(dv * acc[m].x + sb[sub * 8 + 2 * m + 0], 0.f);
        x[2 * m + 1] = fmaxf(dv * acc[m].y + sb[sub * 8 + 2 * m + 1], 0.f);
    }
    // next linear: lane = output col; features f = s4*8+mm live on lane s4 (sub==s4)
    float a2 = 0.f;
    #pragma unroll
    for (int mm = 0; mm < 8; mm++)
        #pragma unroll
        for (int s4 = 0; s4 < 4; s4++) {
            float xv = __shfl_sync(0xffffffffu, x[mm], s4);
            a2 = fmaf(xv, sW[(s4 * 8 + mm) * 33 + lane], a2);
        }
    hs_out[(size_t)node * HID + lane] = __float2half(a2 * dv);
}

// layer-3 aggregate fused with the MLP head
__global__ __launch_bounds__(256) void aggB_kernel(
    const __half* __restrict__ hs_in, float* __restrict__ out,
    const float* __restrict__ bias,
    const float* __restrict__ l1W, const float* __restrict__ l1b,
    const float* __restrict__ l2W, const float* __restrict__ l2b) {
    __shared__ float sW1[32 * 16];
    __shared__ float sW2[16 * 10];
    __shared__ float sb[32], sb1[16], sb2[10];
    int tid = threadIdx.x;
    for (int i = tid; i < 512; i += 256) sW1[i] = l1W[i];
    if (tid < 160) sW2[tid] = l2W[tid];
    if (tid < 32)  sb[tid] = bias[tid];
    if (tid < 16)  sb1[tid] = l1b[tid];
    if (tid < 10)  sb2[tid] = l2b[tid];
    __syncthreads();

    int node = (blockIdx.x * 256 + tid) >> 5;
    int lane = tid & 31;
    int slot = lane >> 2;
    int sub = lane & 3;
    int r0 = g_rowstart[node];
    int r1 = g_rowstart[node + 1];
    float2 acc[4];
    #pragma unroll
    for (int m = 0; m < 4; m++) acc[m] = make_float2(0.f, 0.f);
    int e = r0;
    for (; e + 32 <= r1; e += 32) {
        int idx = g_csr[e + lane];
        #pragma unroll
        for (int j = 0; j < 4; j++) {
            int s = __shfl_sync(0xffffffffu, idx, slot * 4 + j);
            uint4 v = *(const uint4*)&hs_in[(size_t)s * HID + sub * 8];
            __half2* h = (__half2*)&v;
            #pragma unroll
            for (int m = 0; m < 4; m++) {
                float2 f = __half22float2(h[m]);
                acc[m].x += f.x; acc[m].y += f.y;
            }
        }
    }
    int rem = r1 - e;
    if (rem) {
        int idx = (lane < rem) ? g_csr[e + lane] : 0;
        #pragma unroll
        for (int j = 0; j < 4; j++) {
            int t = slot * 4 + j;
            int s = __shfl_sync(0xffffffffu, idx, t);
            if (t < rem) {
                uint4 v = *(const uint4*)&hs_in[(size_t)s * HID + sub * 8];
                __half2* h = (__half2*)&v;
                #pragma unroll
                for (int m = 0; m < 4; m++) {
                    float2 f = __half22float2(h[m]);
                    acc[m].x += f.x; acc[m].y += f.y;
                }
            }
        }
    }
    #pragma unroll
    for (int o = 4; o < 32; o <<= 1) {
        #pragma unroll
        for (int m = 0; m < 4; m++) {
            acc[m].x += __shfl_xor_sync(0xffffffffu, acc[m].x, o);
            acc[m].y += __shfl_xor_sync(0xffffffffu, acc[m].y, o);
        }
    }
    {
        uint4 v = *(const uint4*)&hs_in[(size_t)node * HID + sub * 8];
        __half2* h = (__half2*)&v;
        #pragma unroll
        for (int m = 0; m < 4; m++) {
            float2 f = __half22float2(h[m]);
            acc[m].x += f.x; acc[m].y += f.y;
        }
    }
    float dv = g_dinv[node];
    float x[8];
    #pragma unroll
    for (int m = 0; m < 4; m++) {
        x[2 * m + 0] = fmaxf(dv * acc[m].x + sb[sub * 8 + 2 * m + 0], 0.f);
        x[2 * m + 1] = fmaxf(dv * acc[m].y + sb[sub * 8 + 2 * m + 1], 0.f);
    }
    // head layer 1: col c = lane&15
    int c = lane & 15;
    float t1 = sb1[c];
    #pragma unroll
    for (int mm = 0; mm < 8; mm++)
        #pragma unroll
        for (int s4 = 0; s4 < 4; s4++) {
            float xv = __shfl_sync(0xffffffffu, x[mm], s4);
            t1 = fmaf(xv, sW1[(s4 * 8 + mm) * 16 + c], t1);
        }
    t1 = fmaxf(t1, 0.f);
    // head layer 2: 10 outputs
    int oc = (lane < 10) ? lane : 0;
    float o = sb2[oc];
    #pragma unroll
    for (int c2 = 0; c2 < 16; c2++) {
        float tv = __shfl_sync(0xffffffffu, t1, c2);
        o = fmaf(tv, sW2[c2 * 10 + oc], o);
    }
    if (lane < 10) out[(size_t)node * 10 + lane] = o;
}

// ---------------- launch ----------------

extern "C" void kernel_launch(void* const* d_in, const int* in_sizes, int n_in,
                              void* d_out, int out_size) {
    (void)in_sizes; (void)n_in; (void)out_size;
    const float* x0   = (const float*)d_in[0];
    const int*   edge = (const int*)d_in[1];   // int32 (JAX x64 disabled)
    const float* W1  = (const float*)d_in[3];
    const float* b1  = (const float*)d_in[4];
    const float* W2  = (const float*)d_in[5];
    const float* b2  = (const float*)d_in[6];
    const float* W3  = (const float*)d_in[7];
    const float* b3  = (const float*)d_in[8];
    const float* l1W = (const float*)d_in[9];
    const float* l1b = (const float*)d_in[10];
    const float* l2W = (const float*)d_in[11];
    const float* l2b = (const float*)d_in[12];
    float* out = (float*)d_out;

    __half* hsA; cudaGetSymbolAddress((void**)&hsA, g_hsA);
    __half* hsB; cudaGetSymbolAddress((void**)&hsB, g_hsB);

    // CSR build (single stream — no cross-stream hazards)
    zero_deg_kernel<<<(NN + 255) / 256, 256>>>();
    deg_kernel<<<(NE / 4 + 255) / 256, 256>>>(edge);
    scan1_kernel<<<NBLK_SCAN, 256>>>();
    scan2_kernel<<<1, 128>>>();
    scan3_kernel<<<NBLK_SCAN, 256>>>();
    scatter_kernel<<<(NE / 4 + 255) / 256, 256>>>(edge);

    // layer 1 (dense, reads g_dinv) -> hsA
    gemm1_kernel<<<(NN + 63) / 64, 128>>>(x0, W1);
    // agg1 + W2 linear -> hsB ; agg2 + W3 linear -> hsA ; agg3 + MLP head -> out
    aggA_kernel<<<12500, 256>>>(hsA, hsB, b1, W2);
    aggA_kernel<<<12500, 256>>>(hsB, hsA, b2, W3);
    aggB_kernel<<<12500, 256>>>(hsA, out, b3, l1W, l1b, l2W, l2b);
}